// round 1
// baseline (speedup 1.0000x reference)
#include <cuda_runtime.h>
#include <cuda_bf16.h>
#include <cstdint>

// Problem constants (fixed by the dataset)
#define B 64
#define S 8192
#define C 48
#define L 42
#define IGNORE_LBL (-100)
// N_ARCS = L + L*(L+1) = 1848

// ---------------------------------------------------------------------------
// Device-global scratch (no allocations allowed)
// ---------------------------------------------------------------------------
__device__ float g_start[L];        // log-softmax of A[0:L]
__device__ float g_trans[L * L];    // rows[:, :L]
__device__ float g_fin[L];          // rows[:, L]
__device__ double g_score;          // accumulated numerator score
__device__ int    g_count;          // accumulated valid-token count

// ---------------------------------------------------------------------------
// Kernel 1: build log-softmax tables + zero accumulators. One block.
// Thread r in [0, L] handles one row (r == L -> the start distribution).
// ---------------------------------------------------------------------------
__global__ void crf_tables_kernel(const float* __restrict__ A_scores) {
    int r = threadIdx.x;
    if (r == 0) {
        g_score = 0.0;
        g_count = 0;
    }
    if (r > L) return;

    if (r == L) {
        // start distribution over A[0:L]
        float m = -1e30f;
        for (int j = 0; j < L; j++) m = fmaxf(m, A_scores[j]);
        float sum = 0.0f;
        for (int j = 0; j < L; j++) sum += __expf(A_scores[j] - m);
        float lse = m + __logf(sum);
        for (int j = 0; j < L; j++) g_start[j] = A_scores[j] - lse;
    } else {
        // row r over A[L + r*(L+1) : L + (r+1)*(L+1)]  (L+1 entries)
        const float* row = A_scores + L + r * (L + 1);
        float m = -1e30f;
        for (int j = 0; j <= L; j++) m = fmaxf(m, row[j]);
        float sum = 0.0f;
        for (int j = 0; j <= L; j++) sum += __expf(row[j] - m);
        float lse = m + __logf(sum);
        for (int j = 0; j < L; j++) g_trans[r * L + j] = row[j] - lse;
        g_fin[r] = row[L] - lse;
    }
}

// ---------------------------------------------------------------------------
// Kernel 2: per-row ordered compaction + scoring. One block per batch row.
// blockDim.x = 1024 (32 warps).
// ---------------------------------------------------------------------------
#define ROW_THREADS 1024
#define ROW_WARPS   (ROW_THREADS / 32)

__global__ __launch_bounds__(ROW_THREADS)
void crf_row_kernel(const float* __restrict__ log_probs,
                    const int*   __restrict__ labels) {
    const int b   = blockIdx.x;
    const int tid = threadIdx.x;
    const int lane = tid & 31;
    const int wid  = tid >> 5;

    // comp[t] packs (pos << 8) | y  for the t-th valid token, in order.
    __shared__ uint32_t comp[S];               // 32 KB (worst case: all valid)
    __shared__ float    trans_sh[L * L];       // ~7 KB
    __shared__ float    start_sh[L];
    __shared__ float    fin_sh[L];
    __shared__ int      warp_sums[ROW_WARPS];
    __shared__ double   red[ROW_WARPS];

    // Load transition tables into shared
    for (int i = tid; i < L * L; i += ROW_THREADS) trans_sh[i] = g_trans[i];
    if (tid < L) { start_sh[tid] = g_start[tid]; fin_sh[tid] = g_fin[tid]; }

    // ---- ordered stream compaction of valid (pos, label) pairs ----
    const int* lab = labels + (size_t)b * S;
    int base = 0;
    __syncthreads();

    #pragma unroll
    for (int chunk = 0; chunk < S; chunk += ROW_THREADS) {
        int p = chunk + tid;
        int y = lab[p];
        bool valid = (y != IGNORE_LBL);

        unsigned m = __ballot_sync(0xffffffffu, valid);
        int lane_prefix = __popc(m & ((1u << lane) - 1u));
        if (lane == 0) warp_sums[wid] = __popc(m);
        __syncthreads();

        // inclusive scan of the 32 warp totals by warp 0
        if (wid == 0) {
            int v = warp_sums[lane];
            #pragma unroll
            for (int o = 1; o < 32; o <<= 1) {
                int n = __shfl_up_sync(0xffffffffu, v, o);
                if (lane >= o) v += n;
            }
            warp_sums[lane] = v;   // inclusive
        }
        __syncthreads();

        int woff = (wid == 0) ? 0 : warp_sums[wid - 1];
        if (valid)
            comp[base + woff + lane_prefix] = ((uint32_t)p << 8) | (uint32_t)y;
        base += warp_sums[ROW_WARPS - 1];
        __syncthreads();
    }

    const int count = base;   // number of valid tokens in this row (== T here)

    // ---- scoring: emissions + transitions + start/final ----
    const float* lpb = log_probs + (size_t)b * S * C;
    double local = 0.0;
    for (int t = tid; t < count; t += ROW_THREADS) {
        uint32_t e = comp[t];
        int pos = (int)(e >> 8);
        int y   = (int)(e & 0xFF);          // 1..L
        local += (double)lpb[pos * C + y];  // emission at channel y
        if (t + 1 < count) {
            int y2 = (int)(comp[t + 1] & 0xFF);
            local += (double)trans_sh[(y - 1) * L + (y2 - 1)];
        }
        if (t == 0)         local += (double)start_sh[y - 1];
        if (t == count - 1) local += (double)fin_sh[y - 1];
    }

    // ---- block reduction (double) ----
    #pragma unroll
    for (int o = 16; o > 0; o >>= 1)
        local += __shfl_down_sync(0xffffffffu, local, o);
    if (lane == 0) red[wid] = local;
    __syncthreads();
    if (wid == 0) {
        double v = (lane < ROW_WARPS) ? red[lane] : 0.0;
        #pragma unroll
        for (int o = 16; o > 0; o >>= 1)
            v += __shfl_down_sync(0xffffffffu, v, o);
        if (lane == 0) {
            atomicAdd(&g_score, v);
            atomicAdd(&g_count, count);
        }
    }
}

// ---------------------------------------------------------------------------
// Kernel 3: finalize
// ---------------------------------------------------------------------------
__global__ void crf_finalize_kernel(float* __restrict__ out) {
    out[0] = (float)(g_score / (double)g_count);
}

// ---------------------------------------------------------------------------
// Launch
// ---------------------------------------------------------------------------
extern "C" void kernel_launch(void* const* d_in, const int* in_sizes, int n_in,
                              void* d_out, int out_size) {
    const float* log_probs = (const float*)d_in[0];   // (B, S, C) f32
    const float* A_scores  = (const float*)d_in[1];   // (N_ARCS,) f32
    const int*   labels    = (const int*)d_in[2];     // (B, S) i32
    // d_in[3] = input_lens (unused by the reference computation)
    float* out = (float*)d_out;

    crf_tables_kernel<<<1, 64>>>(A_scores);
    crf_row_kernel<<<B, ROW_THREADS>>>(log_probs, labels);
    crf_finalize_kernel<<<1, 1>>>(out);
}

// round 2
// speedup vs baseline: 1.1448x; 1.1448x over previous
#include <cuda_runtime.h>
#include <cuda_bf16.h>
#include <cstdint>

// Problem constants (fixed by the dataset)
#define B 64
#define S 8192
#define C 48
#define L 42
#define LP1 (L + 1)          // 43
#define IGNORE_LBL (-100)

#define ROW_THREADS 1024
#define ROW_WARPS   (ROW_THREADS / 32)
#define CHUNKS      (S / ROW_THREADS)   // 8

// ---------------------------------------------------------------------------
// Device-global scratch (no allocations allowed)
// ---------------------------------------------------------------------------
__device__ double g_partial[B];      // per-row numerator partial
__device__ int    g_pcount[B];       // per-row valid-token count
__device__ unsigned g_ticket;        // finish counter (reset to 0 by last block)

// ---------------------------------------------------------------------------
// Single fused kernel: one block per batch row.
// ---------------------------------------------------------------------------
__global__ __launch_bounds__(ROW_THREADS)
void crf_fused_kernel(const float* __restrict__ log_probs,
                      const float* __restrict__ A_scores,
                      const int*   __restrict__ labels,
                      float*       __restrict__ out) {
    const int b    = blockIdx.x;
    const int tid  = threadIdx.x;
    const int lane = tid & 31;
    const int wid  = tid >> 5;

    __shared__ float   A_sh[L + L * LP1];     // 1848 floats (raw scores)
    __shared__ float   lse_sh[LP1];           // [0..L-1]=rows, [L]=start
    __shared__ float   trans_sh[L * L];
    __shared__ float   start_sh[L];
    __shared__ float   fin_sh[L];
    __shared__ uint8_t comp[S];               // compacted labels, in order
    __shared__ int     warp_sums[ROW_WARPS];
    __shared__ double  red[ROW_WARPS];
    __shared__ int     is_last;

    // ---- 1. stage A_scores into shared (2 loads/thread) ----
    #pragma unroll
    for (int i = tid; i < L + L * LP1; i += ROW_THREADS) A_sh[i] = A_scores[i];

    // ---- 2. issue all label loads up-front (MLP = 8) ----
    const int* lab = labels + (size_t)b * S;
    int ys[CHUNKS];
    #pragma unroll
    for (int i = 0; i < CHUNKS; i++) ys[i] = lab[tid + i * ROW_THREADS];

    __syncthreads();   // A_sh ready (label loads still in flight)

    // ---- 3. log-sum-exp per table row; warp w handles rows w and w+32 ----
    // Row r < L: entries A_sh[L + r*43 .. L + r*43 + 42]  (43 entries)
    // Row r == L: the start distribution A_sh[0..41]       (42 entries)
    #pragma unroll
    for (int rr = 0; rr < 2; rr++) {
        int r = wid + rr * ROW_WARPS;
        if (r <= L) {
            int n      = (r == L) ? L : LP1;
            const float* row = (r == L) ? A_sh : (A_sh + L + r * LP1);
            float v0 = (lane < n)      ? row[lane]      : -1e30f;
            float v1 = (lane + 32 < n) ? row[lane + 32] : -1e30f;
            float m = fmaxf(v0, v1);
            #pragma unroll
            for (int o = 16; o > 0; o >>= 1)
                m = fmaxf(m, __shfl_xor_sync(0xffffffffu, m, o));
            float s = ((lane < n) ? __expf(v0 - m) : 0.f)
                    + ((lane + 32 < n) ? __expf(v1 - m) : 0.f);
            #pragma unroll
            for (int o = 16; o > 0; o >>= 1)
                s += __shfl_xor_sync(0xffffffffu, s, o);
            if (lane == 0) lse_sh[r] = m + __logf(s);
        }
    }
    __syncthreads();

    // ---- 4. normalized tables into shared ----
    #pragma unroll
    for (int i = tid; i < L * L; i += ROW_THREADS) {
        int r = i / L, c = i % L;
        trans_sh[i] = A_sh[L + r * LP1 + c] - lse_sh[r];
    }
    if (tid < L) {
        start_sh[tid] = A_sh[tid] - lse_sh[L];
        fin_sh[tid]   = A_sh[L + tid * LP1 + L] - lse_sh[tid];
    }

    // ---- 5. emission gather (order-independent), MLP-rich ----
    const float* lpb = log_probs + (size_t)b * S * C;
    float emis[CHUNKS];
    #pragma unroll
    for (int i = 0; i < CHUNKS; i++) {
        int p = tid + i * ROW_THREADS;
        emis[i] = (ys[i] != IGNORE_LBL) ? __ldg(lpb + (size_t)p * C + ys[i]) : 0.0f;
    }
    double local = 0.0;
    #pragma unroll
    for (int i = 0; i < CHUNKS; i++) local += (double)emis[i];

    // ---- 6. ordered compaction of labels into comp[] ----
    int base = 0;
    __syncthreads();   // tables done; comp[] free to write
    #pragma unroll
    for (int i = 0; i < CHUNKS; i++) {
        bool valid = (ys[i] != IGNORE_LBL);
        unsigned m = __ballot_sync(0xffffffffu, valid);
        int lane_prefix = __popc(m & ((1u << lane) - 1u));
        if (lane == 0) warp_sums[wid] = __popc(m);
        __syncthreads();
        if (wid == 0) {
            int v = warp_sums[lane];
            #pragma unroll
            for (int o = 1; o < 32; o <<= 1) {
                int n = __shfl_up_sync(0xffffffffu, v, o);
                if (lane >= o) v += n;
            }
            warp_sums[lane] = v;   // inclusive scan
        }
        __syncthreads();
        int woff = (wid == 0) ? 0 : warp_sums[wid - 1];
        if (valid) comp[base + woff + lane_prefix] = (uint8_t)ys[i];
        base += warp_sums[ROW_WARPS - 1];
        __syncthreads();
    }
    const int count = base;

    // ---- 7. transitions + start/final from shared ----
    for (int t = tid; t < count - 1; t += ROW_THREADS) {
        int y  = comp[t];
        int y2 = comp[t + 1];
        local += (double)trans_sh[(y - 1) * L + (y2 - 1)];
    }
    if (tid == 0 && count > 0) {
        local += (double)start_sh[comp[0] - 1];
        local += (double)fin_sh[comp[count - 1] - 1];
    }

    // ---- 8. block reduction (double) ----
    #pragma unroll
    for (int o = 16; o > 0; o >>= 1)
        local += __shfl_down_sync(0xffffffffu, local, o);
    if (lane == 0) red[wid] = local;
    __syncthreads();
    if (wid == 0) {
        double v = (lane < ROW_WARPS) ? red[lane] : 0.0;
        #pragma unroll
        for (int o = 16; o > 0; o >>= 1)
            v += __shfl_down_sync(0xffffffffu, v, o);
        if (lane == 0) {
            g_partial[b] = v;
            g_pcount[b]  = count;
            __threadfence();
            unsigned t = atomicAdd(&g_ticket, 1u);
            is_last = (t == B - 1) ? 1 : 0;
        }
    }
    __syncthreads();

    // ---- 9. last block finalizes (and resets the ticket for graph replay) ----
    if (is_last && wid == 0) {
        __threadfence();
        double s = (lane < B) ? g_partial[lane] : 0.0;
        double s2 = (lane + 32 < B) ? g_partial[lane + 32] : 0.0;
        int    c = (lane < B) ? g_pcount[lane] : 0;
        int    c2 = (lane + 32 < B) ? g_pcount[lane + 32] : 0;
        s += s2; c += c2;
        #pragma unroll
        for (int o = 16; o > 0; o >>= 1) {
            s += __shfl_down_sync(0xffffffffu, s, o);
            c += __shfl_down_sync(0xffffffffu, c, o);
        }
        if (lane == 0) {
            out[0] = (float)(s / (double)c);
            g_ticket = 0;   // reset for next (graph-replayed) call
        }
    }
}

// ---------------------------------------------------------------------------
// Launch
// ---------------------------------------------------------------------------
extern "C" void kernel_launch(void* const* d_in, const int* in_sizes, int n_in,
                              void* d_out, int out_size) {
    const float* log_probs = (const float*)d_in[0];   // (B, S, C) f32
    const float* A_scores  = (const float*)d_in[1];   // (N_ARCS,) f32
    const int*   labels    = (const int*)d_in[2];     // (B, S) i32
    float* out = (float*)d_out;

    crf_fused_kernel<<<B, ROW_THREADS>>>(log_probs, A_scores, labels, out);
}